// round 3
// baseline (speedup 1.0000x reference)
#include <cuda_runtime.h>
#include <cuda_bf16.h>

// Problem constants
#define NB 256      // batch
#define TT 36       // time length
#define PP 80       // npole
#define FF 50       // features
#define KK 161      // dictionary atoms = 1 + 2*PP
#define KP 164      // K padded to multiple of 4
#define FP 52       // F padded to multiple of 4
#define LAMV 0.1f
#define NITER 100

#define SZ_CODE (NB*KK*FF)   // 2,060,800
#define SZ_D    (TT*KK)      // 5,796
#define SZ_R    (NB*TT*FF)   // 460,800

// ---------------- device scratch (static, no allocations) ----------------
__device__ __align__(16) float  g_Dp[TT*KP];          // padded dictionary [t][k]
__device__             float    g_scal[4];            // 0:Linv 1:wl1 2:wlscale 3:L
__device__ __align__(16) float  g_c[NB*KP*FP];        // DtY * Linv, padded
__device__ __align__(16) float  g_code[NB*KP*FP];     // sparse code, padded
__device__             double   g_part[NB];           // partial sums for ||wn||

// ---------------- 1) build D, compute L = ||DtD||_F ----------------
__global__ void prep_kernel(const float* __restrict__ rr, const float* __restrict__ th) {
    __shared__ float  sD[TT*KP];
    __shared__ double sred[256];
    int tid = threadIdx.x;
    // Build columns: one thread per pole-column pair. Exact iterative r^t.
    for (int k = tid; k < KP; k += 256) {
        if (k == 0) {
            for (int t = 0; t < TT; t++) sD[t*KP] = 1.f;
        } else if (k <= 2*PP) {
            int  p    = (k <= PP) ? (k-1) : (k-1-PP);
            bool isc  = (k <= PP);
            float r = rr[p], a = th[p];
            float rp = 1.f;
            for (int t = 0; t < TT; t++) {
                float ang = (float)t * a;
                sD[t*KP + k] = rp * (isc ? cosf(ang) : sinf(ang));
                rp *= r;
            }
        } else {
            for (int t = 0; t < TT; t++) sD[t*KP + k] = 0.f;
        }
    }
    __syncthreads();
    for (int i = tid; i < TT*KP; i += 256) g_Dp[i] = sD[i];
    double s = 0.0;
    for (int p = tid; p < KK*KK; p += 256) {
        int a = p / KK, b = p % KK;
        float dot = 0.f;
        for (int t = 0; t < TT; t++) dot += sD[t*KP + a] * sD[t*KP + b];
        s += (double)dot * (double)dot;
    }
    sred[tid] = s; __syncthreads();
    for (int st = 128; st > 0; st >>= 1) { if (tid < st) sred[tid] += sred[tid + st]; __syncthreads(); }
    if (tid == 0) {
        float L = (float)sqrt(sred[0]);
        g_scal[3] = L; g_scal[0] = 1.f / L; g_scal[1] = LAMV / L;
    }
}

// ---------------- 2) c = (D^T Y) / L, padded ----------------
__global__ void dty_kernel(const float* __restrict__ x) {
    __shared__ float sD[TT*KP];
    __shared__ float sX[TT*FP];
    int n = blockIdx.x, tid = threadIdx.x;
    for (int i = tid; i < TT*KP; i += 256) sD[i] = g_Dp[i];
    for (int i = tid; i < TT*FP; i += 256) {
        int t = i / FP, f = i % FP;
        sX[i] = (f < FF) ? x[(n*TT + t)*FF + f] : 0.f;
    }
    __syncthreads();
    float Linv = g_scal[0];
    for (int tile = tid; tile < KP*13; tile += 256) {
        int k = tile / 13, f0 = (tile % 13) * 4;
        float4 a = make_float4(0.f, 0.f, 0.f, 0.f);
        for (int t = 0; t < TT; t++) {
            float d = sD[t*KP + k];
            float4 xv = *reinterpret_cast<const float4*>(&sX[t*FP + f0]);
            a.x += d * xv.x; a.y += d * xv.y; a.z += d * xv.z; a.w += d * xv.w;
        }
        a.x *= Linv; a.y *= Linv; a.z *= Linv; a.w *= Linv;
        *reinterpret_cast<float4*>(&g_c[(n*KP + k)*FP + f0]) = a;
    }
}

// ---------------- 3) persistent FISTA: one CTA per sample, smem-resident state ----------------
// smem: sD[36][164] | sy[164][52] | sx[161][52] | sz[36][52] | swl(bf16)[161*50]
// total = 98,704 + 16,100 = 114,804 B  ->  2 CTAs/SM
template<int OUTER>
__global__ void __launch_bounds__(544, 2) fista_kernel() {
    extern __shared__ float sm[];
    float* sD = sm;                    // 5904 floats? no: 36*164 = 5904 elems
    float* sy = sD + TT*KP;            // KP*FP = 8528
    float* sx = sy + KP*FP;            // KK*FP = 8372
    float* sz = sx + KK*FP;            // TT*FP = 1872
    __nv_bfloat16* swl = reinterpret_cast<__nv_bfloat16*>(sz + TT*FP);

    int n = blockIdx.x, tid = threadIdx.x;
    float Linv = g_scal[0];
    float wl1  = g_scal[1];

    for (int i = tid; i < TT*KP; i += 544) sD[i] = g_Dp[i];
    for (int i = tid; i < KP*FP; i += 544) sy[i] = 0.f;
    for (int i = tid; i < KK*FP; i += 544) sx[i] = 0.f;
    if (OUTER == 2) {
        float wls = g_scal[2];
        for (int e = tid; e < KK*FF; e += 544) {
            int k = e / FF, f = e % FF;
            float c0 = g_code[(n*KP + k)*FP + f];
            swl[e] = __float2bfloat16(wls / (fabsf(c0) + 0.01f));
        }
    }

    // u-phase tile: 4k x 4f, 41*13 = 533 tiles
    bool au  = (tid < 533);
    int  ukt = tid / 13, uf0 = (tid % 13) * 4, uk0 = ukt * 4;
    // z-phase tile: 1t x 4f, 36*13 = 468 tiles
    bool az  = (tid < 468);
    int  zt  = tid / 13, zf0 = (tid % 13) * 4;

    // hoist c for owned elements into registers (constant across iterations)
    float creg[16];
    if (au) {
        #pragma unroll
        for (int r = 0; r < 4; r++)
            #pragma unroll
            for (int j = 0; j < 4; j++)
                creg[r*4 + j] = g_c[(n*KP + uk0 + r)*FP + uf0 + j];
    }

    float tprev = 1.f;
    __syncthreads();

    for (int it = 0; it < NITER; it++) {
        // ---- z = D * y  (36 x Fp) ----
        if (az) {
            float4 a = make_float4(0.f, 0.f, 0.f, 0.f);
            const float* drow = &sD[zt*KP];
            #pragma unroll 2
            for (int k4 = 0; k4 < KP; k4 += 4) {
                float4 d  = *reinterpret_cast<const float4*>(&drow[k4]);
                float4 y0 = *reinterpret_cast<const float4*>(&sy[(k4+0)*FP + zf0]);
                a.x += d.x*y0.x; a.y += d.x*y0.y; a.z += d.x*y0.z; a.w += d.x*y0.w;
                float4 y1 = *reinterpret_cast<const float4*>(&sy[(k4+1)*FP + zf0]);
                a.x += d.y*y1.x; a.y += d.y*y1.y; a.z += d.y*y1.z; a.w += d.y*y1.w;
                float4 y2 = *reinterpret_cast<const float4*>(&sy[(k4+2)*FP + zf0]);
                a.x += d.z*y2.x; a.y += d.z*y2.y; a.z += d.z*y2.z; a.w += d.z*y2.w;
                float4 y3 = *reinterpret_cast<const float4*>(&sy[(k4+3)*FP + zf0]);
                a.x += d.w*y3.x; a.y += d.w*y3.y; a.z += d.w*y3.z; a.w += d.w*y3.w;
            }
            *reinterpret_cast<float4*>(&sz[zt*FP + zf0]) = a;
        }
        __syncthreads();

        float tnew = 0.5f * (1.f + sqrtf(1.f + 4.f * tprev * tprev));
        float beta = (tprev - 1.f) / tnew;
        tprev = tnew;

        // ---- u = D^T * z ; shrink + momentum ----
        if (au) {
            float acc[16];
            #pragma unroll
            for (int i = 0; i < 16; i++) acc[i] = 0.f;
            #pragma unroll 2
            for (int t = 0; t < TT; t++) {
                float4 z = *reinterpret_cast<const float4*>(&sz[t*FP + uf0]);
                // consume dictionary column-by-column to cap live registers
                float d0 = sD[t*KP + uk0 + 0];
                acc[ 0] += d0*z.x; acc[ 1] += d0*z.y; acc[ 2] += d0*z.z; acc[ 3] += d0*z.w;
                float d1 = sD[t*KP + uk0 + 1];
                acc[ 4] += d1*z.x; acc[ 5] += d1*z.y; acc[ 6] += d1*z.z; acc[ 7] += d1*z.w;
                float d2 = sD[t*KP + uk0 + 2];
                acc[ 8] += d2*z.x; acc[ 9] += d2*z.y; acc[10] += d2*z.z; acc[11] += d2*z.w;
                float d3 = sD[t*KP + uk0 + 3];
                acc[12] += d3*z.x; acc[13] += d3*z.y; acc[14] += d3*z.z; acc[15] += d3*z.w;
            }
            #pragma unroll
            for (int r = 0; r < 4; r++) {
                int k = uk0 + r;
                if (k < KK) {
                    #pragma unroll
                    for (int j = 0; j < 4; j++) {
                        int f = uf0 + j;
                        if (f < FF) {
                            int idx = k*FP + f;
                            float Ay = sy[idx] - Linv * acc[r*4 + j];
                            float v  = Ay + creg[r*4 + j];
                            float wl = (OUTER == 1) ? wl1 : __bfloat162float(swl[k*FF + f]);
                            float xn = fmaxf(0.f, v - wl) + fminf(0.f, v + wl);
                            float xo = sx[idx];
                            sy[idx] = xn + beta * (xn - xo);
                            sx[idx] = xn;
                        }
                    }
                }
            }
        }
        __syncthreads();
    }

    // write padded code (zeros in pads)
    for (int i = tid; i < KP*FP; i += 544) {
        int k = i / FP, f = i % FP;
        float v = (k < KK && f < FF) ? sx[i] : 0.f;
        g_code[n*KP*FP + i] = v;
    }
}

// ---------------- 4) deterministic ||wn||^2 partials ----------------
__global__ void reduce_part_kernel() {
    __shared__ double sr[256];
    int n = blockIdx.x, tid = threadIdx.x;
    double s = 0.0;
    for (int e = tid; e < KK*FF; e += 256) {
        int k = e / FF, f = e % FF;
        float c = g_code[(n*KP + k)*FP + f];
        float wn = 1.f / (fabsf(c) + 0.01f);
        s += (double)wn * (double)wn;
    }
    sr[tid] = s; __syncthreads();
    for (int st = 128; st > 0; st >>= 1) { if (tid < st) sr[tid] += sr[tid + st]; __syncthreads(); }
    if (tid == 0) g_part[n] = sr[0];
}

__global__ void reduce_final_kernel() {
    __shared__ double sr[256];
    int tid = threadIdx.x;
    sr[tid] = g_part[tid]; __syncthreads();
    for (int st = 128; st > 0; st >>= 1) { if (tid < st) sr[tid] += sr[tid + st]; __syncthreads(); }
    if (tid == 0) {
        double nw = sqrt(sr[0]);
        g_scal[2] = (float)((double)LAMV * (double)KK * (double)g_scal[0] / nw);
    }
}

// ---------------- 5) outputs: code | D | reconst = D @ code ----------------
__global__ void final_kernel(float* __restrict__ out, int mode) {
    extern __shared__ float fsm[];
    float* sD = fsm;             // TT*KP
    float* sc = fsm + TT*KP;     // KK*FP
    int n = blockIdx.x, tid = threadIdx.x;
    if (n == NB) {
        if (mode == 0) {
            for (int i = tid; i < TT*KK; i += 256) {
                int t = i / KK, k = i % KK;
                out[SZ_CODE + i] = g_Dp[t*KP + k];
            }
        }
        return;
    }
    for (int i = tid; i < TT*KP; i += 256) sD[i] = g_Dp[i];
    for (int i = tid; i < KK*FP; i += 256) sc[i] = g_code[n*KP*FP + i];
    __syncthreads();
    if (mode <= 1) {
        for (int e = tid; e < KK*FF; e += 256) {
            int k = e / FF, f = e % FF;
            out[(long)n*KK*FF + e] = sc[k*FP + f];
        }
    }
    if (mode == 0 || mode == 2) {
        long base = (mode == 0) ? (long)SZ_CODE + SZ_D : 0;
        for (int tile = tid; tile < TT*13; tile += 256) {
            int t = tile / 13, f0 = (tile % 13) * 4;
            float4 a = make_float4(0.f, 0.f, 0.f, 0.f);
            for (int k = 0; k < KK; k++) {
                float d = sD[t*KP + k];
                float4 cv = *reinterpret_cast<const float4*>(&sc[k*FP + f0]);
                a.x += d * cv.x; a.y += d * cv.y; a.z += d * cv.z; a.w += d * cv.w;
            }
            long o = base + (long)n*TT*FF + t*FF + f0;
            out[o] = a.x;
            if (f0 + 1 < FF) out[o+1] = a.y;
            if (f0 + 2 < FF) out[o+2] = a.z;
            if (f0 + 3 < FF) out[o+3] = a.w;
        }
    }
}

// ---------------- launch ----------------
extern "C" void kernel_launch(void* const* d_in, const int* in_sizes, int n_in,
                              void* d_out, int out_size) {
    const float* x  = (const float*)d_in[0];
    const float* rr = (const float*)d_in[1];
    const float* th = (const float*)d_in[2];
    float* out = (float*)d_out;

    int mode = 0;                                 // code + D + reconst
    if (out_size == SZ_CODE) mode = 1;            // code only
    else if (out_size == SZ_R) mode = 2;          // reconst only

    const int SM_FISTA = (TT*KP + KP*FP + KK*FP + TT*FP) * 4 + KK*FF * 2; // 114,804
    const int SM_FINAL = (TT*KP + KK*FP) * 4;                             // 57,104

    cudaFuncSetAttribute(fista_kernel<1>, cudaFuncAttributeMaxDynamicSharedMemorySize, SM_FISTA);
    cudaFuncSetAttribute(fista_kernel<2>, cudaFuncAttributeMaxDynamicSharedMemorySize, SM_FISTA);
    cudaFuncSetAttribute(final_kernel,    cudaFuncAttributeMaxDynamicSharedMemorySize, SM_FINAL);

    prep_kernel<<<1, 256>>>(rr, th);
    dty_kernel<<<NB, 256>>>(x);
    fista_kernel<1><<<NB, 544, SM_FISTA>>>();
    reduce_part_kernel<<<NB, 256>>>();
    reduce_final_kernel<<<1, 256>>>();
    fista_kernel<2><<<NB, 544, SM_FISTA>>>();
    final_kernel<<<NB + 1, 256, SM_FINAL>>>(out, mode);
}

// round 4
// speedup vs baseline: 1.5439x; 1.5439x over previous
#include <cuda_runtime.h>
#include <cuda_bf16.h>

// Problem constants
#define NB 256      // batch
#define TT 36       // time length
#define PP 80       // npole
#define FF 50       // features
#define KK 161      // dictionary atoms = 1 + 2*PP
#define KP 164      // K padded to multiple of 4
#define FP 52       // F padded to multiple of 4
#define LAMV 0.1f
#define NITER 100

#define SZ_CODE (NB*KK*FF)   // 2,060,800
#define SZ_D    (TT*KK)      // 5,796
#define SZ_R    (NB*TT*FF)   // 460,800

// ---------------- device scratch (static, no allocations) ----------------
__device__ __align__(16) float  g_Dp[TT*KP];          // padded dictionary [t][k]
__device__             float    g_scal[4];            // 0:Linv 1:wl1 2:wlscale 3:L
__device__ __align__(16) float  g_c[NB*KP*FP];        // DtY * Linv, padded
__device__ __align__(16) float  g_code[NB*KP*FP];     // sparse code, padded
__device__             double   g_part[NB];           // partial sums for ||wn||

// ---------------- 1) build D, compute L = ||DtD||_F ----------------
__global__ void prep_kernel(const float* __restrict__ rr, const float* __restrict__ th) {
    __shared__ float  sD[TT*KP];
    __shared__ double sred[256];
    int tid = threadIdx.x;
    for (int k = tid; k < KP; k += 256) {
        if (k == 0) {
            for (int t = 0; t < TT; t++) sD[t*KP] = 1.f;
        } else if (k <= 2*PP) {
            int  p   = (k <= PP) ? (k-1) : (k-1-PP);
            bool isc = (k <= PP);
            float r = rr[p], a = th[p];
            float rp = 1.f;
            for (int t = 0; t < TT; t++) {
                float ang = (float)t * a;
                sD[t*KP + k] = rp * (isc ? cosf(ang) : sinf(ang));
                rp *= r;
            }
        } else {
            for (int t = 0; t < TT; t++) sD[t*KP + k] = 0.f;
        }
    }
    __syncthreads();
    for (int i = tid; i < TT*KP; i += 256) g_Dp[i] = sD[i];
    double s = 0.0;
    for (int p = tid; p < KK*KK; p += 256) {
        int a = p / KK, b = p % KK;
        float dot = 0.f;
        for (int t = 0; t < TT; t++) dot += sD[t*KP + a] * sD[t*KP + b];
        s += (double)dot * (double)dot;
    }
    sred[tid] = s; __syncthreads();
    for (int st = 128; st > 0; st >>= 1) { if (tid < st) sred[tid] += sred[tid + st]; __syncthreads(); }
    if (tid == 0) {
        float L = (float)sqrt(sred[0]);
        g_scal[3] = L; g_scal[0] = 1.f / L; g_scal[1] = LAMV / L;
    }
}

// ---------------- 2) c = (D^T Y) / L, padded ----------------
__global__ void dty_kernel(const float* __restrict__ x) {
    __shared__ float sD[TT*KP];
    __shared__ float sX[TT*FP];
    int n = blockIdx.x, tid = threadIdx.x;
    for (int i = tid; i < TT*KP; i += 256) sD[i] = g_Dp[i];
    for (int i = tid; i < TT*FP; i += 256) {
        int t = i / FP, f = i % FP;
        sX[i] = (f < FF) ? x[(n*TT + t)*FF + f] : 0.f;
    }
    __syncthreads();
    float Linv = g_scal[0];
    for (int tile = tid; tile < KP*13; tile += 256) {
        int k = tile / 13, f0 = (tile % 13) * 4;
        float4 a = make_float4(0.f, 0.f, 0.f, 0.f);
        for (int t = 0; t < TT; t++) {
            float d = sD[t*KP + k];
            float4 xv = *reinterpret_cast<const float4*>(&sX[t*FP + f0]);
            a.x += d * xv.x; a.y += d * xv.y; a.z += d * xv.z; a.w += d * xv.w;
        }
        a.x *= Linv; a.y *= Linv; a.z *= Linv; a.w *= Linv;
        *reinterpret_cast<float4*>(&g_c[(n*KP + k)*FP + f0]) = a;
    }
}

// ---------------- 3) persistent FISTA: one CTA per sample, smem-resident state ----------------
// smem floats: sD[36*164]=23616B | sy[164*52]=34112B | sx[161*52]=33488B | sz[36*52]=7488B
//              swl bf16[161*52]=16744B   total = 115,448 B  -> 2 CTAs/SM
template<int OUTER>
__global__ void __launch_bounds__(544, 2) fista_kernel() {
    extern __shared__ float sm[];
    float* sD = sm;                    // TT*KP
    float* sy = sD + TT*KP;            // KP*FP
    float* sx = sy + KP*FP;            // KK*FP
    float* sz = sx + KK*FP;            // TT*FP
    __nv_bfloat16* swl = reinterpret_cast<__nv_bfloat16*>(sz + TT*FP);  // KK*FP

    int n = blockIdx.x, tid = threadIdx.x;
    float Linv = g_scal[0];
    float wl1  = g_scal[1];

    for (int i = tid; i < TT*KP; i += 544) sD[i] = g_Dp[i];
    for (int i = tid; i < KP*FP; i += 544) sy[i] = 0.f;
    for (int i = tid; i < KK*FP; i += 544) sx[i] = 0.f;
    if (OUTER == 2) {
        float wls = g_scal[2];
        for (int e = tid; e < KK*FP; e += 544) {
            float c0 = g_code[n*KP*FP + (e/FP)*FP + (e%FP)];
            swl[e] = __float2bfloat16(wls / (fabsf(c0) + 0.01f));
        }
    }

    // u-phase tile: 4k x 4f, 41*13 = 533 tiles
    bool au  = (tid < 533);
    int  uk0 = (tid / 13) * 4, uf0 = (tid % 13) * 4;
    // z-phase tile: 2t x 4f, 18*13 = 234 tiles
    bool az  = (tid < 234);
    int  zt0 = (tid / 13) * 2, zf0 = (tid % 13) * 4;

    const float4* cg = reinterpret_cast<const float4*>(&g_c[(n*KP + uk0)*FP + uf0]);

    float tprev = 1.f;
    __syncthreads();

    for (int it = 0; it < NITER; it++) {
        // ---- z = D * y : each thread 2 t-rows x 4 f-cols ----
        if (az) {
            float4 a0 = make_float4(0.f,0.f,0.f,0.f);
            float4 a1 = make_float4(0.f,0.f,0.f,0.f);
            const float* d0r = &sD[(zt0+0)*KP];
            const float* d1r = &sD[(zt0+1)*KP];
            #pragma unroll 2
            for (int k4 = 0; k4 < KP; k4 += 4) {
                float4 d0 = *reinterpret_cast<const float4*>(&d0r[k4]);
                float4 d1 = *reinterpret_cast<const float4*>(&d1r[k4]);
                float4 y0 = *reinterpret_cast<const float4*>(&sy[(k4+0)*FP + zf0]);
                a0.x += d0.x*y0.x; a0.y += d0.x*y0.y; a0.z += d0.x*y0.z; a0.w += d0.x*y0.w;
                a1.x += d1.x*y0.x; a1.y += d1.x*y0.y; a1.z += d1.x*y0.z; a1.w += d1.x*y0.w;
                float4 y1 = *reinterpret_cast<const float4*>(&sy[(k4+1)*FP + zf0]);
                a0.x += d0.y*y1.x; a0.y += d0.y*y1.y; a0.z += d0.y*y1.z; a0.w += d0.y*y1.w;
                a1.x += d1.y*y1.x; a1.y += d1.y*y1.y; a1.z += d1.y*y1.z; a1.w += d1.y*y1.w;
                float4 y2 = *reinterpret_cast<const float4*>(&sy[(k4+2)*FP + zf0]);
                a0.x += d0.z*y2.x; a0.y += d0.z*y2.y; a0.z += d0.z*y2.z; a0.w += d0.z*y2.w;
                a1.x += d1.z*y2.x; a1.y += d1.z*y2.y; a1.z += d1.z*y2.z; a1.w += d1.z*y2.w;
                float4 y3 = *reinterpret_cast<const float4*>(&sy[(k4+3)*FP + zf0]);
                a0.x += d0.w*y3.x; a0.y += d0.w*y3.y; a0.z += d0.w*y3.z; a0.w += d0.w*y3.w;
                a1.x += d1.w*y3.x; a1.y += d1.w*y3.y; a1.z += d1.w*y3.z; a1.w += d1.w*y3.w;
            }
            *reinterpret_cast<float4*>(&sz[(zt0+0)*FP + zf0]) = a0;
            *reinterpret_cast<float4*>(&sz[(zt0+1)*FP + zf0]) = a1;
        }
        __syncthreads();

        float tnew = 0.5f * (1.f + sqrtf(1.f + 4.f * tprev * tprev));
        float beta = (tprev - 1.f) / tnew;
        tprev = tnew;

        // ---- u = D^T * z ; shrink + momentum ----
        if (au) {
            // prefetch c (iteration-constant, L2-resident) — overlaps t-loop
            float4 c0 = __ldg(cg + 0*(FP/4));
            float4 c1 = __ldg(cg + 1*(FP/4));
            float4 c2 = __ldg(cg + 2*(FP/4));
            float4 c3 = __ldg(cg + 3*(FP/4));
            float acc[16];
            #pragma unroll
            for (int i = 0; i < 16; i++) acc[i] = 0.f;
            #pragma unroll 2
            for (int t = 0; t < TT; t++) {
                float4 z = *reinterpret_cast<const float4*>(&sz[t*FP + uf0]);
                float4 d = *reinterpret_cast<const float4*>(&sD[t*KP + uk0]);
                acc[ 0] += d.x*z.x; acc[ 1] += d.x*z.y; acc[ 2] += d.x*z.z; acc[ 3] += d.x*z.w;
                acc[ 4] += d.y*z.x; acc[ 5] += d.y*z.y; acc[ 6] += d.y*z.z; acc[ 7] += d.y*z.w;
                acc[ 8] += d.z*z.x; acc[ 9] += d.z*z.y; acc[10] += d.z*z.z; acc[11] += d.z*z.w;
                acc[12] += d.w*z.x; acc[13] += d.w*z.y; acc[14] += d.w*z.z; acc[15] += d.w*z.w;
            }
            float cr[16] = { c0.x,c0.y,c0.z,c0.w, c1.x,c1.y,c1.z,c1.w,
                             c2.x,c2.y,c2.z,c2.w, c3.x,c3.y,c3.z,c3.w };
            #pragma unroll
            for (int r = 0; r < 4; r++) {
                int k = uk0 + r;
                if (k < KK) {
                    int idx = k*FP + uf0;
                    float4 yv = *reinterpret_cast<const float4*>(&sy[idx]);
                    float4 xv = *reinterpret_cast<const float4*>(&sx[idx]);
                    float wlv[4];
                    if (OUTER == 1) {
                        wlv[0]=wl1; wlv[1]=wl1; wlv[2]=wl1; wlv[3]=wl1;
                    } else {
                        __nv_bfloat162 w01 = *reinterpret_cast<const __nv_bfloat162*>(&swl[idx]);
                        __nv_bfloat162 w23 = *reinterpret_cast<const __nv_bfloat162*>(&swl[idx+2]);
                        wlv[0]=__bfloat162float(w01.x); wlv[1]=__bfloat162float(w01.y);
                        wlv[2]=__bfloat162float(w23.x); wlv[3]=__bfloat162float(w23.y);
                    }
                    float xn[4], yo[4] = {yv.x, yv.y, yv.z, yv.w}, xo[4] = {xv.x, xv.y, xv.z, xv.w};
                    #pragma unroll
                    for (int j = 0; j < 4; j++) {
                        float v = yo[j] - Linv * acc[r*4 + j] + cr[r*4 + j];
                        xn[j] = fmaxf(0.f, v - wlv[j]) + fminf(0.f, v + wlv[j]);
                    }
                    float4 ny = make_float4(xn[0] + beta*(xn[0]-xo[0]), xn[1] + beta*(xn[1]-xo[1]),
                                            xn[2] + beta*(xn[2]-xo[2]), xn[3] + beta*(xn[3]-xo[3]));
                    *reinterpret_cast<float4*>(&sy[idx]) = ny;
                    *reinterpret_cast<float4*>(&sx[idx]) = make_float4(xn[0],xn[1],xn[2],xn[3]);
                }
            }
        }
        __syncthreads();
    }

    // write padded code (zeros in pads)
    for (int i = tid; i < KP*FP; i += 544) {
        int k = i / FP;
        float v = (k < KK) ? sx[i] : 0.f;
        g_code[n*KP*FP + i] = v;
    }
}

// ---------------- 4) deterministic ||wn||^2 partials ----------------
__global__ void reduce_part_kernel() {
    __shared__ double sr[256];
    int n = blockIdx.x, tid = threadIdx.x;
    double s = 0.0;
    for (int e = tid; e < KK*FF; e += 256) {
        int k = e / FF, f = e % FF;
        float c = g_code[(n*KP + k)*FP + f];
        float wn = 1.f / (fabsf(c) + 0.01f);
        s += (double)wn * (double)wn;
    }
    sr[tid] = s; __syncthreads();
    for (int st = 128; st > 0; st >>= 1) { if (tid < st) sr[tid] += sr[tid + st]; __syncthreads(); }
    if (tid == 0) g_part[n] = sr[0];
}

__global__ void reduce_final_kernel() {
    __shared__ double sr[256];
    int tid = threadIdx.x;
    sr[tid] = g_part[tid]; __syncthreads();
    for (int st = 128; st > 0; st >>= 1) { if (tid < st) sr[tid] += sr[tid + st]; __syncthreads(); }
    if (tid == 0) {
        double nw = sqrt(sr[0]);
        g_scal[2] = (float)((double)LAMV * (double)KK * (double)g_scal[0] / nw);
    }
}

// ---------------- 5) outputs: code | D | reconst = D @ code ----------------
__global__ void final_kernel(float* __restrict__ out, int mode) {
    extern __shared__ float fsm[];
    float* sD = fsm;             // TT*KP
    float* sc = fsm + TT*KP;     // KK*FP
    int n = blockIdx.x, tid = threadIdx.x;
    if (n == NB) {
        if (mode == 0) {
            for (int i = tid; i < TT*KK; i += 256) {
                int t = i / KK, k = i % KK;
                out[SZ_CODE + i] = g_Dp[t*KP + k];
            }
        }
        return;
    }
    for (int i = tid; i < TT*KP; i += 256) sD[i] = g_Dp[i];
    for (int i = tid; i < KK*FP; i += 256) sc[i] = g_code[n*KP*FP + i];
    __syncthreads();
    if (mode <= 1) {
        for (int e = tid; e < KK*FF; e += 256) {
            int k = e / FF, f = e % FF;
            out[(long)n*KK*FF + e] = sc[k*FP + f];
        }
    }
    if (mode == 0 || mode == 2) {
        long base = (mode == 0) ? (long)SZ_CODE + SZ_D : 0;
        for (int tile = tid; tile < TT*13; tile += 256) {
            int t = tile / 13, f0 = (tile % 13) * 4;
            float4 a = make_float4(0.f, 0.f, 0.f, 0.f);
            for (int k = 0; k < KK; k++) {
                float d = sD[t*KP + k];
                float4 cv = *reinterpret_cast<const float4*>(&sc[k*FP + f0]);
                a.x += d * cv.x; a.y += d * cv.y; a.z += d * cv.z; a.w += d * cv.w;
            }
            long o = base + (long)n*TT*FF + t*FF + f0;
            out[o] = a.x;
            if (f0 + 1 < FF) out[o+1] = a.y;
            if (f0 + 2 < FF) out[o+2] = a.z;
            if (f0 + 3 < FF) out[o+3] = a.w;
        }
    }
}

// ---------------- launch ----------------
extern "C" void kernel_launch(void* const* d_in, const int* in_sizes, int n_in,
                              void* d_out, int out_size) {
    const float* x  = (const float*)d_in[0];
    const float* rr = (const float*)d_in[1];
    const float* th = (const float*)d_in[2];
    float* out = (float*)d_out;

    int mode = 0;                                 // code + D + reconst
    if (out_size == SZ_CODE) mode = 1;            // code only
    else if (out_size == SZ_R) mode = 2;          // reconst only

    const int SM_FISTA = (TT*KP + KP*FP + KK*FP + TT*FP) * 4 + KK*FP * 2; // 115,448
    const int SM_FINAL = (TT*KP + KK*FP) * 4;                             // 57,104

    cudaFuncSetAttribute(fista_kernel<1>, cudaFuncAttributeMaxDynamicSharedMemorySize, SM_FISTA);
    cudaFuncSetAttribute(fista_kernel<2>, cudaFuncAttributeMaxDynamicSharedMemorySize, SM_FISTA);
    cudaFuncSetAttribute(final_kernel,    cudaFuncAttributeMaxDynamicSharedMemorySize, SM_FINAL);

    prep_kernel<<<1, 256>>>(rr, th);
    dty_kernel<<<NB, 256>>>(x);
    fista_kernel<1><<<NB, 544, SM_FISTA>>>();
    reduce_part_kernel<<<NB, 256>>>();
    reduce_final_kernel<<<1, 256>>>();
    fista_kernel<2><<<NB, 544, SM_FISTA>>>();
    final_kernel<<<NB + 1, 256, SM_FINAL>>>(out, mode);
}